// round 3
// baseline (speedup 1.0000x reference)
#include <cuda_runtime.h>

// MultiLabelRankingLoss: out = sum_b sum_{n in neg(b), p in pos(b)} relu(s[b,n]-s[b,p]+1)
//                              / sum_b |neg(b)|*|pos(b)|
// B=2048, D=256, K=8. Index buffer may be int32 (JAX x64 disabled) or int64;
// autodetect on device, all reads bounds-safe under either interpretation.

#define D_FIXED 256
#define B_MAX   4096

__device__ float        g_loss_part[B_MAX];
__device__ int          g_pairs_part[B_MAX];
__device__ unsigned int g_count = 0;   // completion counter; last block resets it

__global__ __launch_bounds__(256, 8)
void mlrl_kernel(const float* __restrict__ scores,
                 const int* __restrict__ idx_words,   // raw 32-bit view of index buffer
                 float* __restrict__ out,
                 int B, int K)
{
    const int D = D_FIXED;
    __shared__ float s[D_FIXED];
    __shared__ int   flag[D_FIXED];
    __shared__ float pos_s[32];
    __shared__ int   n_pos_sh;
    __shared__ float red[256];
    __shared__ int   pred[256];
    __shared__ bool  is_last;
    __shared__ int   is64_sh;

    const int b = blockIdx.x;
    const int t = threadIdx.x;

    // Load this sample's score row and clear the positive mask.
    s[t]    = scores[b * D + t];
    flag[t] = 0;
    if (t == 0) n_pos_sh = 0;

    // --- dtype autodetect (thread 0): look at the first 2 rows as if int64.
    // int64 little-endian with values in [0,256) => words [2j]=v<256, [2j+1]=0.
    // All 4*K word reads are in-bounds: buffer holds >= B*K >= 4*K int32 words.
    if (t == 0) {
        int looks64 = 1;
        for (int j = 0; j < 2 * K; j++) {
            int lo = idx_words[2 * j];
            int hi = idx_words[2 * j + 1];
            if (hi != 0 || lo < 0 || lo >= D) { looks64 = 0; break; }
        }
        is64_sh = looks64;
    }
    __syncthreads();

    const int is64 = is64_sh;

    // Mark positives. Duplicate indices -> same slot, race is benign.
    if (t < K) {
        int word_pos = is64 ? 2 * (b * K + t) : (b * K + t);
        int idx = idx_words[word_pos];
        idx &= (D - 1);                // hard guard (values are 0..D-1 anyway)
        flag[idx] = 1;
    }
    __syncthreads();

    // Compact unique positive scores into pos_s[0..npos).
    if (flag[t]) {
        int i = atomicAdd(&n_pos_sh, 1);
        if (i < 32) pos_s[i] = s[t];
    }
    __syncthreads();

    int npos = n_pos_sh;
    if (npos > 32) npos = 32;

    // Each negative developer accumulates hinge vs. every unique positive.
    float local = 0.0f;
    if (!flag[t]) {
        const float sv = s[t] + 1.0f;   // s_neg + margin
        #pragma unroll 8
        for (int j = 0; j < npos; j++)
            local += fmaxf(sv - pos_s[j], 0.0f);
    }

    // Block tree reduction (fixed order -> deterministic).
    red[t] = local;
    __syncthreads();
    #pragma unroll
    for (int off = 128; off > 0; off >>= 1) {
        if (t < off) red[t] += red[t + off];
        __syncthreads();
    }

    if (t == 0) {
        g_loss_part[b]  = red[0];
        g_pairs_part[b] = npos * (D - npos);
        __threadfence();
        unsigned int c = atomicAdd(&g_count, 1u);
        is_last = (c == (unsigned int)gridDim.x - 1u);
    }
    __syncthreads();

    // Last block to finish: reduce all partials, write scalar, reset counter.
    if (is_last) {
        float lsum = 0.0f;
        int   psum = 0;
        for (int i = t; i < B; i += 256) {
            lsum += g_loss_part[i];
            psum += g_pairs_part[i];
        }
        red[t]  = lsum;
        pred[t] = psum;
        __syncthreads();
        #pragma unroll
        for (int off = 128; off > 0; off >>= 1) {
            if (t < off) { red[t] += red[t + off]; pred[t] += pred[t + off]; }
            __syncthreads();
        }
        if (t == 0) {
            int tp = pred[0];
            out[0] = (tp > 0) ? (red[0] / (float)tp) : 0.0f;
            g_count = 0;   // replay-safe reset for CUDA-graph re-execution
        }
    }
}

extern "C" void kernel_launch(void* const* d_in, const int* in_sizes, int n_in,
                              void* d_out, int out_size)
{
    const float* scores    = (const float*)d_in[0];
    const int*   idx_words = (const int*)d_in[1];   // raw 32-bit view (int32 or int64 halves)
    const int D = D_FIXED;
    const int B = in_sizes[0] / D;
    const int K = in_sizes[1] / B;

    mlrl_kernel<<<B, 256>>>(scores, idx_words, (float*)d_out, B, K);
}

// round 5
// speedup vs baseline: 1.1935x; 1.1935x over previous
#include <cuda_runtime.h>

// MultiLabelRankingLoss: out = sum_b sum_{n in neg(b), p in pos(b)} relu(s[b,n]-s[b,p]+1)
//                              / sum_b |neg(b)|*|pos(b)|
// B=2048, D=256, K=8. Warp-per-sample, barrier-free hot path.
// Index buffer may be int32 or int64 (JAX x64 flag); autodetected per-warp via ballot.

#define D_FIXED 256
#define K_FIXED 8
#define WARPS_PER_CTA 8
#define GRID_MAX 4096

__device__ float        g_loss_part[GRID_MAX];
__device__ int          g_pairs_part[GRID_MAX];
__device__ unsigned int g_count = 0;   // completion counter; last block resets it

__global__ __launch_bounds__(256)
void mlrl_kernel(const float* __restrict__ scores,
                 const int* __restrict__ idx_words,   // raw 32-bit view of index buffer
                 float* __restrict__ out,
                 int B)
{
    const int D = D_FIXED;
    const int K = K_FIXED;
    const int lane = threadIdx.x & 31;
    const int warp = threadIdx.x >> 5;
    const int b = blockIdx.x * WARPS_PER_CTA + warp;

    __shared__ float s_loss[WARPS_PER_CTA];
    __shared__ int   s_pairs[WARPS_PER_CTA];
    __shared__ bool  is_last;

    // ---- dtype autodetect (warp-local, no barrier) ----
    // int64 little-endian with values in [0,256): words[2j] in [0,256), words[2j+1]==0.
    // Check the first 16 logical values; in-bounds under either interpretation.
    int ok = 1;
    if (lane < 16) {
        int lo = idx_words[2 * lane];
        int hi = idx_words[2 * lane + 1];
        ok = (hi == 0 && lo >= 0 && lo < D) ? 1 : 0;
    }
    unsigned bal = __ballot_sync(0xFFFFFFFFu, ok);
    const int is64 = ((bal & 0xFFFFu) == 0xFFFFu) ? 1 : 0;

    float warp_loss = 0.0f;
    int   warp_pairs = 0;

    if (b < B) {
        // Lane owns developers [lane*8, lane*8+8): two float4 loads, coalesced.
        const float4* row = (const float4*)(scores + (size_t)b * D);
        float4 v0 = row[lane * 2];
        float4 v1 = row[lane * 2 + 1];

        // Lanes 0..7: load index j and gather its score (L1/L2 hit).
        int   idx_l = 0;
        float pos_l = 0.0f;
        if (lane < K) {
            int wp = is64 ? 2 * (b * K + lane) : (b * K + lane);
            idx_l = idx_words[wp] & (D - 1);          // hard guard
            pos_l = scores[(size_t)b * D + idx_l];
        }

        int   idxs[K_FIXED];
        float ps[K_FIXED];
        #pragma unroll
        for (int j = 0; j < K; j++) {
            idxs[j] = __shfl_sync(0xFFFFFFFFu, idx_l, j);
            ps[j]   = __shfl_sync(0xFFFFFFFFu, pos_l, j);
        }

        // Dedup (uniform across warp): keep first occurrence only.
        int npos = 0;
        #pragma unroll
        for (int j = 0; j < K; j++) {
            bool keep = true;
            #pragma unroll
            for (int j2 = 0; j2 < K; j2++)
                if (j2 < j && idxs[j2] == idxs[j]) keep = false;
            if (keep) npos++;
            else      ps[j] = 1.0e30f;   // sentinel: a - 1e30 < 0 -> relu = 0
        }

        // Positive mask for this lane's 8 slots (duplicates set same bit).
        unsigned pm = 0;
        #pragma unroll
        for (int j = 0; j < K; j++)
            if ((idxs[j] >> 3) == lane) pm |= 1u << (idxs[j] & 7);

        // a_k = s_k + margin for negatives, -inf sentinel for positive slots.
        float a[8];
        a[0] = (pm &   1u) ? -1.0e30f : v0.x + 1.0f;
        a[1] = (pm &   2u) ? -1.0e30f : v0.y + 1.0f;
        a[2] = (pm &   4u) ? -1.0e30f : v0.z + 1.0f;
        a[3] = (pm &   8u) ? -1.0e30f : v0.w + 1.0f;
        a[4] = (pm &  16u) ? -1.0e30f : v1.x + 1.0f;
        a[5] = (pm &  32u) ? -1.0e30f : v1.y + 1.0f;
        a[6] = (pm &  64u) ? -1.0e30f : v1.z + 1.0f;
        a[7] = (pm & 128u) ? -1.0e30f : v1.w + 1.0f;

        // 64-term hinge, fully unrolled, branch-free.
        float acc = 0.0f;
        #pragma unroll
        for (int k = 0; k < 8; k++) {
            #pragma unroll
            for (int j = 0; j < K; j++)
                acc += fmaxf(a[k] - ps[j], 0.0f);
        }

        // Warp tree reduction (deterministic order).
        #pragma unroll
        for (int off = 16; off > 0; off >>= 1)
            acc += __shfl_xor_sync(0xFFFFFFFFu, acc, off);

        warp_loss  = acc;
        warp_pairs = npos * (D - npos);
    }

    if (lane == 0) {
        s_loss[warp]  = warp_loss;
        s_pairs[warp] = warp_pairs;
    }
    __syncthreads();

    if (threadIdx.x == 0) {
        float bl = 0.0f; int bp = 0;
        #pragma unroll
        for (int w = 0; w < WARPS_PER_CTA; w++) { bl += s_loss[w]; bp += s_pairs[w]; }
        g_loss_part[blockIdx.x]  = bl;
        g_pairs_part[blockIdx.x] = bp;
        __threadfence();
        unsigned int c = atomicAdd(&g_count, 1u);
        is_last = (c == (unsigned int)gridDim.x - 1u);
    }
    __syncthreads();

    // Last block: reduce all block partials, write scalar, reset counter.
    if (is_last) {
        const int G = gridDim.x;
        float lsum = 0.0f; int psum = 0;
        for (int i = threadIdx.x; i < G; i += 256) {
            lsum += g_loss_part[i];
            psum += g_pairs_part[i];
        }
        // Warp reduce then cross-warp via shared.
        #pragma unroll
        for (int off = 16; off > 0; off >>= 1) {
            lsum += __shfl_xor_sync(0xFFFFFFFFu, lsum, off);
            psum += __shfl_xor_sync(0xFFFFFFFFu, psum, off);
        }
        if (lane == 0) { s_loss[warp] = lsum; s_pairs[warp] = psum; }
        __syncthreads();
        if (threadIdx.x == 0) {
            float tl = 0.0f; int tp = 0;
            #pragma unroll
            for (int w = 0; w < WARPS_PER_CTA; w++) { tl += s_loss[w]; tp += s_pairs[w]; }
            out[0] = (tp > 0) ? (tl / (float)tp) : 0.0f;
            g_count = 0;   // replay-safe reset for CUDA-graph re-execution
        }
    }
}

extern "C" void kernel_launch(void* const* d_in, const int* in_sizes, int n_in,
                              void* d_out, int out_size)
{
    const float* scores    = (const float*)d_in[0];
    const int*   idx_words = (const int*)d_in[1];
    const int D = D_FIXED;
    const int B = in_sizes[0] / D;
    const int grid = (B + WARPS_PER_CTA - 1) / WARPS_PER_CTA;

    mlrl_kernel<<<grid, 256>>>(scores, idx_words, (float*)d_out, B);
}

// round 6
// speedup vs baseline: 1.3062x; 1.0945x over previous
#include <cuda_runtime.h>

// MultiLabelRankingLoss: out = sum_b sum_{n in neg(b), p in pos(b)} relu(s[b,n]-s[b,p]+1)
//                              / sum_b |neg(b)|*|pos(b)|
// B=2048, D=256, K=8. Warp-per-sample; no dependent gather (register shuffle
// extraction), atomic-accumulator tail. Index dtype (int32/int64) autodetected.

#define D_FIXED 256
#define K_FIXED 8
#define WARPS_PER_CTA 8

__device__ float        g_loss_acc  = 0.0f;
__device__ int          g_pairs_acc = 0;
__device__ unsigned int g_count     = 0;   // completion counter; last block resets all

__device__ __forceinline__ float sel8(int sub, float4 v0, float4 v1)
{
    // Uniform 8-way register select: returns element `sub` of {v0.x..v1.w}.
    float lo01 = (sub & 1) ? v0.y : v0.x;
    float lo23 = (sub & 1) ? v0.w : v0.z;
    float hi01 = (sub & 1) ? v1.y : v1.x;
    float hi23 = (sub & 1) ? v1.w : v1.z;
    float lo = (sub & 2) ? lo23 : lo01;
    float hi = (sub & 2) ? hi23 : hi01;
    return (sub & 4) ? hi : lo;
}

__global__ __launch_bounds__(256)
void mlrl_kernel(const float* __restrict__ scores,
                 const int* __restrict__ idx_words,   // raw 32-bit view of index buffer
                 float* __restrict__ out,
                 int B)
{
    const int D = D_FIXED;
    const int K = K_FIXED;
    const int lane = threadIdx.x & 31;
    const int warp = threadIdx.x >> 5;
    const int b = blockIdx.x * WARPS_PER_CTA + warp;

    __shared__ float s_loss[WARPS_PER_CTA];
    __shared__ int   s_pairs[WARPS_PER_CTA];

    // ---- dtype autodetect (warp-local, overlaps with row loads below) ----
    // int64 LE with values in [0,256): words[2j] in [0,256), words[2j+1]==0.
    int ok = 1;
    if (lane < 8) {
        int lo = idx_words[2 * lane];
        int hi = idx_words[2 * lane + 1];
        ok = (hi == 0 && lo >= 0 && lo < D) ? 1 : 0;
    }
    unsigned bal = __ballot_sync(0xFFFFFFFFu, ok);
    const int is64 = ((bal & 0xFFu) == 0xFFu) ? 1 : 0;

    float warp_loss = 0.0f;
    int   warp_pairs = 0;

    if (b < B) {
        // Lane owns developers [lane*8, lane*8+8): two float4 loads, coalesced.
        const float4* row = (const float4*)(scores + (size_t)b * D);
        float4 v0 = row[lane * 2];
        float4 v1 = row[lane * 2 + 1];

        // Lanes 0..7 load the raw index words (independent of row loads).
        int idx_l = 0;
        if (lane < K) {
            int wp = is64 ? 2 * (b * K + lane) : (b * K + lane);
            idx_l = idx_words[wp] & (D - 1);          // hard guard
        }

        int idxs[K_FIXED];
        #pragma unroll
        for (int j = 0; j < K; j++)
            idxs[j] = __shfl_sync(0xFFFFFFFFu, idx_l, j);

        // Extract positive scores from registers: element idx&7 of lane idx>>3.
        // No memory dependency — pure ALU + shuffle.
        float ps[K_FIXED];
        #pragma unroll
        for (int j = 0; j < K; j++) {
            float cand = sel8(idxs[j] & 7, v0, v1);
            ps[j] = __shfl_sync(0xFFFFFFFFu, cand, idxs[j] >> 3);
        }

        // Dedup (uniform across warp): keep first occurrence only.
        int npos = 0;
        #pragma unroll
        for (int j = 0; j < K; j++) {
            bool keep = true;
            #pragma unroll
            for (int j2 = 0; j2 < K; j2++)
                if (j2 < j && idxs[j2] == idxs[j]) keep = false;
            if (keep) npos++;
            else      ps[j] = 1.0e30f;   // sentinel: relu(a - 1e30) = 0
        }

        // Positive mask for this lane's 8 slots.
        unsigned pm = 0;
        #pragma unroll
        for (int j = 0; j < K; j++)
            if ((idxs[j] >> 3) == lane) pm |= 1u << (idxs[j] & 7);

        // a_k = s_k + margin for negatives, -inf sentinel for positive slots.
        float a[8];
        a[0] = (pm &   1u) ? -1.0e30f : v0.x + 1.0f;
        a[1] = (pm &   2u) ? -1.0e30f : v0.y + 1.0f;
        a[2] = (pm &   4u) ? -1.0e30f : v0.z + 1.0f;
        a[3] = (pm &   8u) ? -1.0e30f : v0.w + 1.0f;
        a[4] = (pm &  16u) ? -1.0e30f : v1.x + 1.0f;
        a[5] = (pm &  32u) ? -1.0e30f : v1.y + 1.0f;
        a[6] = (pm &  64u) ? -1.0e30f : v1.z + 1.0f;
        a[7] = (pm & 128u) ? -1.0e30f : v1.w + 1.0f;

        // 64-term hinge, fully unrolled, branch-free.
        float acc = 0.0f;
        #pragma unroll
        for (int k = 0; k < 8; k++) {
            #pragma unroll
            for (int j = 0; j < K; j++)
                acc += fmaxf(a[k] - ps[j], 0.0f);
        }

        // Warp tree reduction.
        #pragma unroll
        for (int off = 16; off > 0; off >>= 1)
            acc += __shfl_xor_sync(0xFFFFFFFFu, acc, off);

        warp_loss  = acc;
        warp_pairs = npos * (D - npos);
    }

    if (lane == 0) {
        s_loss[warp]  = warp_loss;
        s_pairs[warp] = warp_pairs;
    }
    __syncthreads();

    if (threadIdx.x == 0) {
        float bl = 0.0f; int bp = 0;
        #pragma unroll
        for (int w = 0; w < WARPS_PER_CTA; w++) { bl += s_loss[w]; bp += s_pairs[w]; }
        atomicAdd(&g_loss_acc,  bl);
        atomicAdd(&g_pairs_acc, bp);
        __threadfence();
        unsigned int c = atomicAdd(&g_count, 1u);
        if (c == (unsigned int)gridDim.x - 1u) {
            // All blocks' accumulator atomics are globally visible.
            __threadfence();
            float tl = g_loss_acc;
            int   tp = g_pairs_acc;
            out[0] = (tp > 0) ? (tl / (float)tp) : 0.0f;
            // Reset for CUDA-graph replay.
            g_loss_acc  = 0.0f;
            g_pairs_acc = 0;
            g_count     = 0;
        }
    }
}

extern "C" void kernel_launch(void* const* d_in, const int* in_sizes, int n_in,
                              void* d_out, int out_size)
{
    const float* scores    = (const float*)d_in[0];
    const int*   idx_words = (const int*)d_in[1];
    const int B = in_sizes[0] / D_FIXED;
    const int grid = (B + WARPS_PER_CTA - 1) / WARPS_PER_CTA;

    mlrl_kernel<<<grid, 256>>>(scores, idx_words, (float*)d_out, B);
}

// round 9
// speedup vs baseline: 1.4373x; 1.1004x over previous
#include <cuda_runtime.h>

// MultiLabelRankingLoss: out = sum_b sum_{n in neg(b), p in pos(b)} relu(s[b,n]-s[b,p]+1)
//                              / sum_b |neg(b)|*|pos(b)|
// B=2048, D=256, K=8, indices int32 (established: int64 interpretation faulted in R1;
// autodetect in R2-R5 always selected int32). Warp-per-sample, all loads issue at T=0,
// register-shuffle positive extraction, release/acquire atomic tail (no CCTL.IVALL).

#define D_FIXED 256
#define K_FIXED 8
#define WARPS_PER_CTA 8

__device__ float        g_loss_acc  = 0.0f;
__device__ int          g_pairs_acc = 0;
__device__ unsigned int g_count     = 0;   // completion counter; last thread resets all

__device__ __forceinline__ float sel8(int sub, float4 v0, float4 v1)
{
    // Uniform 8-way register select: element `sub` of {v0.x..v1.w}.
    float lo01 = (sub & 1) ? v0.y : v0.x;
    float lo23 = (sub & 1) ? v0.w : v0.z;
    float hi01 = (sub & 1) ? v1.y : v1.x;
    float hi23 = (sub & 1) ? v1.w : v1.z;
    float lo = (sub & 2) ? lo23 : lo01;
    float hi = (sub & 2) ? hi23 : hi01;
    return (sub & 4) ? hi : lo;
}

__global__ __launch_bounds__(256)
void mlrl_kernel(const float* __restrict__ scores,
                 const int* __restrict__ pos_idx,     // int32 indices
                 float* __restrict__ out,
                 int B)
{
    const int D = D_FIXED;
    const int K = K_FIXED;
    const int lane = threadIdx.x & 31;
    const int warp = threadIdx.x >> 5;
    const int b = blockIdx.x * WARPS_PER_CTA + warp;

    __shared__ float s_loss[WARPS_PER_CTA];
    __shared__ int   s_pairs[WARPS_PER_CTA];

    float warp_loss = 0.0f;
    int   warp_pairs = 0;

    if (b < B) {
        // All three loads independent -> issue together at T=0.
        const float4* row = (const float4*)(scores + (size_t)b * D);
        float4 v0 = row[lane * 2];
        float4 v1 = row[lane * 2 + 1];

        int idx_l = 0;
        if (lane < K)
            idx_l = pos_idx[b * K + lane] & (D - 1);   // hard guard

        int idxs[K_FIXED];
        #pragma unroll
        for (int j = 0; j < K; j++)
            idxs[j] = __shfl_sync(0xFFFFFFFFu, idx_l, j);

        // Positive scores from registers: element idx&7 of lane idx>>3. No gather.
        float ps[K_FIXED];
        #pragma unroll
        for (int j = 0; j < K; j++) {
            float cand = sel8(idxs[j] & 7, v0, v1);
            ps[j] = __shfl_sync(0xFFFFFFFFu, cand, idxs[j] >> 3);
        }

        // Dedup (uniform across warp): keep first occurrence only.
        int npos = 0;
        #pragma unroll
        for (int j = 0; j < K; j++) {
            bool keep = true;
            #pragma unroll
            for (int j2 = 0; j2 < K; j2++)
                if (j2 < j && idxs[j2] == idxs[j]) keep = false;
            if (keep) npos++;
            else      ps[j] = 1.0e30f;   // sentinel: relu(a - 1e30) = 0
        }

        // Positive mask for this lane's 8 slots.
        unsigned pm = 0;
        #pragma unroll
        for (int j = 0; j < K; j++)
            if ((idxs[j] >> 3) == lane) pm |= 1u << (idxs[j] & 7);

        // a_k = s_k + margin for negatives, -inf sentinel for positive slots.
        float a[8];
        a[0] = (pm &   1u) ? -1.0e30f : v0.x + 1.0f;
        a[1] = (pm &   2u) ? -1.0e30f : v0.y + 1.0f;
        a[2] = (pm &   4u) ? -1.0e30f : v0.z + 1.0f;
        a[3] = (pm &   8u) ? -1.0e30f : v0.w + 1.0f;
        a[4] = (pm &  16u) ? -1.0e30f : v1.x + 1.0f;
        a[5] = (pm &  32u) ? -1.0e30f : v1.y + 1.0f;
        a[6] = (pm &  64u) ? -1.0e30f : v1.z + 1.0f;
        a[7] = (pm & 128u) ? -1.0e30f : v1.w + 1.0f;

        // 64-term hinge, fully unrolled, branch-free.
        float acc = 0.0f;
        #pragma unroll
        for (int k = 0; k < 8; k++) {
            #pragma unroll
            for (int j = 0; j < K; j++)
                acc += fmaxf(a[k] - ps[j], 0.0f);
        }

        // Warp tree reduction.
        #pragma unroll
        for (int off = 16; off > 0; off >>= 1)
            acc += __shfl_xor_sync(0xFFFFFFFFu, acc, off);

        warp_loss  = acc;
        warp_pairs = npos * (D - npos);
    }

    if (lane == 0) {
        s_loss[warp]  = warp_loss;
        s_pairs[warp] = warp_pairs;
    }
    __syncthreads();

    if (threadIdx.x == 0) {
        float bl = 0.0f; int bp = 0;
        #pragma unroll
        for (int w = 0; w < WARPS_PER_CTA; w++) { bl += s_loss[w]; bp += s_pairs[w]; }

        // Relaxed reductions for the accumulators, release on the counter:
        // the release orders this block's adds before its count increment,
        // so the thread observing count==grid-1 sees all adds. No full
        // __threadfence() -> no CCTL.IVALL L1 flush on sm_103a.
        asm volatile("red.relaxed.gpu.global.add.f32 [%0], %1;"
                     :: "l"(&g_loss_acc), "f"(bl) : "memory");
        asm volatile("red.relaxed.gpu.global.add.s32 [%0], %1;"
                     :: "l"(&g_pairs_acc), "r"(bp) : "memory");

        unsigned int c;
        asm volatile("atom.release.gpu.global.add.u32 %0, [%1], %2;"
                     : "=r"(c) : "l"(&g_count), "r"(1u) : "memory");

        if (c == (unsigned int)gridDim.x - 1u) {
            float tl; int tp;
            asm volatile("ld.acquire.gpu.global.f32 %0, [%1];"
                         : "=f"(tl) : "l"(&g_loss_acc) : "memory");
            asm volatile("ld.acquire.gpu.global.s32 %0, [%1];"
                         : "=r"(tp) : "l"(&g_pairs_acc) : "memory");
            out[0] = (tp > 0) ? (tl / (float)tp) : 0.0f;
            // Reset for CUDA-graph replay (kernel boundary orders these
            // before the next replay's atomics).
            g_loss_acc  = 0.0f;
            g_pairs_acc = 0;
            g_count     = 0;
        }
    }
}

extern "C" void kernel_launch(void* const* d_in, const int* in_sizes, int n_in,
                              void* d_out, int out_size)
{
    const float* scores  = (const float*)d_in[0];
    const int*   pos_idx = (const int*)d_in[1];
    const int B = in_sizes[0] / D_FIXED;
    const int grid = (B + WARPS_PER_CTA - 1) / WARPS_PER_CTA;

    mlrl_kernel<<<grid, 256>>>(scores, pos_idx, (float*)d_out, B);
}